// round 11
// baseline (speedup 1.0000x reference)
#include <cuda_runtime.h>
#include <math.h>

// EntmaxBisect, alpha=1.5, d=4096, 50 bisection iters, p = 1/(d-1) (faithful).
//
// Analytic collapse (validated R1/R5, rel_err 4.6e-8): with p = 1/4095, every
// nonzero Z term u^p lies in [0.975, 1.0001], so the reference fp32 mask
// (sum(Z) - 1 >= 0) is exactly:
//     count(Xs > t) >= 2                         <=>  t < s2
//  || count == 1 && (m - t)^p rounds to >= 1.0f  <=>  fl(m - t) >= U_TH
// Bisection needs only per-row (max, second-max); runs on thread 0 only.
//
// R6 changes (R5: 86us, DRAM 73.7%, issue 34.4%, achieved occ 65.7%):
//  - 512 threads/CTA, VPT=8: ~30 regs -> 4 CTAs/SM = 64 warps (100% theor.
//    occ, was 87.5%); 2x co-resident CTAs hide the serial bisection bubble
//  - dropped the 4th __syncthreads: every thread folds the 16 warp sums in
//    a fixed order (deterministic) and computes 1/bsum itself
//  - __ldcs/__stcs streaming hints (zero reuse: 536MB through 126MB L2)
// Numerics: m/s2 exact extrema (order-invariant) -> t bit-identical to R5;
// only the ~2-term Z-sum association changes (effect ~1e-7 << 1e-3).
//
// (R11 = R6 resubmitted: broker timeouts in R6-R10; the R6 kernel has
//  never run. Unchanged to preserve delta attribution.)

#define NTHREADS 512
#define DIM_D 4096
#define VPT 8            // 2 x float4 per thread
#define NWARPS (NTHREADS / 32)

__global__ __launch_bounds__(NTHREADS)
void entmax_bisect_kernel(const float* __restrict__ X, float* __restrict__ Y) {
    const int tid = threadIdx.x;
    const int lane = tid & 31, wid = tid >> 5;
    const size_t row_off = (size_t)blockIdx.x * DIM_D;
    const float4* __restrict__ x4 = reinterpret_cast<const float4*>(X + row_off);
    float4* __restrict__ y4 = reinterpret_cast<float4*>(Y + row_off);

    __shared__ float sh_hi[NWARPS];
    __shared__ float sh_lo[NWARPS];
    __shared__ float sh_sum[NWARPS];
    __shared__ float sh_t;

    // ---- load row (raw; the 0.5 scale folds into later FMAs exactly) ----
    float xs[VPT];
#pragma unroll
    for (int j = 0; j < 2; j++) {
        float4 v = __ldcs(&x4[tid + j * NTHREADS]);
        xs[4 * j + 0] = v.x;
        xs[4 * j + 1] = v.y;
        xs[4 * j + 2] = v.z;
        xs[4 * j + 3] = v.w;
    }

    // ---- branch-free per-thread top-2 (FMNMX only, no predicates) ----
    float hi = -INFINITY, lo = -INFINITY;
#pragma unroll
    for (int i = 0; i < VPT; i++) {
        float v = xs[i];
        lo = fmaxf(lo, fminf(hi, v));
        hi = fmaxf(hi, v);
    }
    const float thd_hi = hi;  // keep: thread-level sparsity test later

    // ---- warp top-2 (symmetric butterfly combine) ----
#pragma unroll
    for (int off = 16; off > 0; off >>= 1) {
        float h2 = __shfl_xor_sync(0xFFFFFFFFu, hi, off);
        float l2 = __shfl_xor_sync(0xFFFFFFFFu, lo, off);
        if (h2 >= hi) { lo = fmaxf(hi, l2); hi = h2; }
        else          { lo = fmaxf(lo, h2); }
    }
    if (lane == 0) { sh_hi[wid] = hi; sh_lo[wid] = lo; }
    __syncthreads();

    // ---- thread 0: fold warps, scale, run the exact fp32 bisection ----
    if (tid == 0) {
        float mr = -INFINITY, s2r = -INFINITY;
#pragma unroll
        for (int w = 0; w < NWARPS; w++) {
            float h2 = sh_hi[w];
            if (h2 >= mr) { s2r = fmaxf(mr, sh_lo[w]); mr = h2; }
            else          { s2r = fmaxf(s2r, h2); }
        }
        const float m  = 0.5f * mr;   // exact: matches per-element 0.5*x max
        const float s2 = 0.5f * s2r;

        float t_min = m - 1.0f;
        float t_max = m - 0.015625f;  // m - d^(1-alpha) = m - 1/64
        float diff  = t_max - t_min;
        const float U_TH = 0.99987796f;  // (m-t)^(1/4095) rounds to >= 1.0f
        float t = t_min;
#pragma unroll
        for (int it = 0; it < 50; it++) {
            diff = diff * 0.5f;
            t = t_min + diff;
            if ((t < s2) || ((m - t) >= U_TH)) t_min = t;
        }
        sh_t = t;  // Z is taken at the LAST probe t (scan carries t)
    }
    __syncthreads();
    const float t = sh_t;

    // ---- sum(Z): only threads whose max survives do any pow work ----
    const float P = 1.0f / 4095.0f;
    const float thd_u = fmaf(0.5f, thd_hi, -t);  // == fl(0.5*hi) - t bitwise
    float lsum = 0.0f;
    if (thd_u > 0.0f) {
#pragma unroll
        for (int i = 0; i < VPT; i++) {
            float u = fmaf(0.5f, xs[i], -t);
            if (u > 0.0f) lsum += exp2f(P * log2f(u));
        }
    }
#pragma unroll
    for (int off = 16; off > 0; off >>= 1)
        lsum += __shfl_xor_sync(0xFFFFFFFFu, lsum, off);
    if (lane == 0) sh_sum[wid] = lsum;
    __syncthreads();

    // every thread folds the warp sums in the same fixed order (deterministic,
    // identical result in all threads) -> no extra barrier for a broadcast
    float bsum = 0.0f;
#pragma unroll
    for (int w = 0; w < NWARPS; w++) bsum += sh_sum[w];
    const float inv = 1.0f / bsum;

    // ---- write: zero fast path for the ~510/512 all-zero threads ----
    if (thd_u > 0.0f) {
#pragma unroll
        for (int j = 0; j < 2; j++) {
            float4 v;
#pragma unroll
            for (int k = 0; k < 4; k++) {
                float u = fmaf(0.5f, xs[4 * j + k], -t);
                float zi = 0.0f;
                if (u > 0.0f) zi = exp2f(P * log2f(u)) * inv;
                (&v.x)[k] = zi;
            }
            __stcs(&y4[tid + j * NTHREADS], v);
        }
    } else {
        const float4 z4 = make_float4(0.0f, 0.0f, 0.0f, 0.0f);
#pragma unroll
        for (int j = 0; j < 2; j++)
            __stcs(&y4[tid + j * NTHREADS], z4);
    }
}

extern "C" void kernel_launch(void* const* d_in, const int* in_sizes, int n_in,
                              void* d_out, int out_size) {
    const float* X = (const float*)d_in[0];
    float* Y = (float*)d_out;
    const int nrows = in_sizes[0] / DIM_D;   // 8*2048 = 16384
    entmax_bisect_kernel<<<nrows, NTHREADS>>>(X, Y);
}